// round 4
// baseline (speedup 1.0000x reference)
#include <cuda_runtime.h>
#include <cstdint>

// Problem constants
#define Bn 4
#define Ln 512
#define Hn 768
#define En 10
#define Rn 10

// GEMM tiling: CTA 128x256, 8 warps of 64x64, BK=32, 3-stage cp.async
#define BM 128
#define BN 256
#define BK 32
#define NSTAGES 3
#define NTHR 256
#define SROW 36                            // padded row stride (floats)
#define A_BYTES (BM * SROW * 4)            // 18432
#define B_BYTES (BN * SROW * 4)            // 36864
#define STAGE_BYTES (A_BYTES + B_BYTES)    // 55296
#define SMEM_BYTES (NSTAGES * STAGE_BYTES) // 165888

// ---------------- scratch (device globals: allocation-guard safe) ----------
__device__ float g_hr[Bn * Ln * Hn];        // rounded h
__device__ float g_wpr[Hn * Hn];            // rounded W_proj
__device__ float g_wbr[Rn * Hn * Hn];       // rounded W_bil
__device__ float g_hproj[Bn * Ln * Hn];     // hproj (tf32-rounded)
__device__ float g_t[Bn * Rn * Ln * Hn];    // t (tf32-rounded)

// ---------------- helpers ----------------------------------------------------
__device__ __forceinline__ uint32_t smem_u32(const void* p) {
    uint32_t a;
    asm("{ .reg .u64 t; cvta.to.shared.u64 t, %1; cvt.u32.u64 %0, t; }" : "=r"(a) : "l"(p));
    return a;
}

__device__ __forceinline__ void cp16(uint32_t saddr, const void* g) {
    asm volatile("cp.async.cg.shared.global [%0], [%1], 16;" :: "r"(saddr), "l"(g));
}
#define CP_COMMIT() asm volatile("cp.async.commit_group;" ::: "memory")
#define CP_WAIT1()  asm volatile("cp.async.wait_group 1;" ::: "memory")

__device__ __forceinline__ float rtf32(float x) {
    uint32_t u;
    asm("cvt.rna.tf32.f32 %0, %1;" : "=r"(u) : "f"(x));
    return __uint_as_float(u);
}

__device__ __forceinline__ void mma8(float* c, const uint32_t* a, const uint32_t* b) {
    asm volatile(
        "mma.sync.aligned.m16n8k8.row.col.f32.tf32.tf32.f32 "
        "{%0,%1,%2,%3}, {%4,%5,%6,%7}, {%8,%9}, {%0,%1,%2,%3};"
        : "+f"(c[0]), "+f"(c[1]), "+f"(c[2]), "+f"(c[3])
        : "r"(a[0]), "r"(a[1]), "r"(a[2]), "r"(a[3]), "r"(b[0]), "r"(b[1]));
}

// ---------------- tf32 mma.sync GEMM ------------------------------------------
// C[row, col] = sum_k A[za][row,k] * B[zb][col,k]   (A,B both K-major)
// za = z / 10, zb = z % bZmod
// C addr: C + (z/10)*cZ1 + (z%10)*cZ2 + row*sCm + col*sCn
// mode: 1=relu, 2=round-to-tf32, 4=bias[col], 8=bias[z%10]
__global__ void __launch_bounds__(NTHR, 1) gemm_mma(
    const float* __restrict__ A, long sAz,
    const float* __restrict__ B, int bZmod, long sBz,
    float* __restrict__ C, long cZ1, long cZ2, long sCm, long sCn,
    const float* __restrict__ bias, int mode, int K)
{
    extern __shared__ __align__(16) char smem[];
    const uint32_t sbase = smem_u32(smem);
    const int tid = threadIdx.x;
    const int z = blockIdx.z;
    const int m0 = blockIdx.y * BM;
    const int n0 = blockIdx.x * BN;
    const int nk = K / BK;

    const float* Ag = A + (long)(z / 10) * sAz + (long)m0 * K;
    const float* Bg = B + (long)(z % bZmod) * sBz + (long)n0 * K;

    const int wid = tid >> 5;
    const int lane = tid & 31;
    const int warp_m = wid >> 2;      // 0..1 -> 64 rows
    const int warp_n = wid & 3;       // 0..3 -> 64 cols
    const int g = lane >> 2;          // 0..7
    const int t = lane & 3;           // 0..3

    float acc[4][8][4];
#pragma unroll
    for (int mi = 0; mi < 4; ++mi)
#pragma unroll
        for (int ni = 0; ni < 8; ++ni)
#pragma unroll
            for (int q = 0; q < 4; ++q) acc[mi][ni][q] = 0.0f;

    // stage loader: A 1024 chunks + B 2048 chunks of 16B; 12 per thread
    auto load_stage = [&](int s, int k0) {
        const uint32_t sA = sbase + s * STAGE_BYTES;
        const uint32_t sB = sA + A_BYTES;
#pragma unroll
        for (int it = 0; it < 4; ++it) {
            const int idx = tid + it * NTHR;
            const int row = idx >> 3;
            const int seg = idx & 7;
            cp16(sA + (uint32_t)(row * SROW + seg * 4) * 4, Ag + (long)row * K + k0 + seg * 4);
        }
#pragma unroll
        for (int it = 0; it < 8; ++it) {
            const int idx = tid + it * NTHR;
            const int row = idx >> 3;
            const int seg = idx & 7;
            cp16(sB + (uint32_t)(row * SROW + seg * 4) * 4, Bg + (long)row * K + k0 + seg * 4);
        }
    };

    // prefetch
    load_stage(0, 0); CP_COMMIT();
    if (nk > 1) load_stage(1, BK);
    CP_COMMIT();

    for (int i = 0; i < nk; ++i) {
        CP_WAIT1();
        __syncthreads();
        if (i + 2 < nk) load_stage((i + 2) % NSTAGES, (i + 2) * BK);
        CP_COMMIT();

        const int s = i % NSTAGES;
        const float* As = (const float*)(smem + s * STAGE_BYTES);
        const float* Bs = (const float*)(smem + s * STAGE_BYTES + A_BYTES);
        const float* Aw = As + (warp_m * 64) * SROW;
        const float* Bw = Bs + (warp_n * 64) * SROW;

#pragma unroll
        for (int ks = 0; ks < BK; ks += 8) {
            uint32_t af[4][4], bf[8][2];
#pragma unroll
            for (int mi = 0; mi < 4; ++mi) {
                const float* p = Aw + (mi * 16 + g) * SROW + ks + t;
                af[mi][0] = __float_as_uint(p[0]);
                af[mi][1] = __float_as_uint(p[8 * SROW]);
                af[mi][2] = __float_as_uint(p[4]);
                af[mi][3] = __float_as_uint(p[8 * SROW + 4]);
            }
#pragma unroll
            for (int ni = 0; ni < 8; ++ni) {
                const float* p = Bw + (ni * 8 + g) * SROW + ks + t;
                bf[ni][0] = __float_as_uint(p[0]);
                bf[ni][1] = __float_as_uint(p[4]);
            }
#pragma unroll
            for (int mi = 0; mi < 4; ++mi)
#pragma unroll
                for (int ni = 0; ni < 8; ++ni)
                    mma8(acc[mi][ni], af[mi], bf[ni]);
        }
    }

    // ---------------- epilogue ----------------
    float bz = 0.0f;
    if (mode & 8) bz = bias[z % 10];
    float* Cz = C + (long)(z / 10) * cZ1 + (long)(z % 10) * cZ2;

#pragma unroll
    for (int mi = 0; mi < 4; ++mi) {
        const long r0 = m0 + warp_m * 64 + mi * 16 + g;
#pragma unroll
        for (int ni = 0; ni < 8; ++ni) {
            const long col = n0 + warp_n * 64 + ni * 8 + 2 * t;
            float v[4];
#pragma unroll
            for (int q = 0; q < 4; ++q) v[q] = acc[mi][ni][q];
            if (mode & 4) {
                const float b0v = bias[col], b1v = bias[col + 1];
                v[0] += b0v; v[1] += b1v; v[2] += b0v; v[3] += b1v;
            }
            if (mode & 8) { v[0] += bz; v[1] += bz; v[2] += bz; v[3] += bz; }
            if (mode & 1) {
#pragma unroll
                for (int q = 0; q < 4; ++q) v[q] = fmaxf(v[q], 0.0f);
            }
            if (mode & 2) {
#pragma unroll
                for (int q = 0; q < 4; ++q) v[q] = rtf32(v[q]);
            }
            if (sCn == 1) {
                *(float2*)(Cz + r0 * sCm + col) = make_float2(v[0], v[1]);
                *(float2*)(Cz + (r0 + 8) * sCm + col) = make_float2(v[2], v[3]);
            } else {
                float* p0 = Cz + r0 * sCm + col * sCn;
                float* p1 = Cz + (r0 + 8) * sCm + col * sCn;
                p0[0] = v[0]; p0[sCn] = v[1];
                p1[0] = v[2]; p1[sCn] = v[3];
            }
        }
    }
}

// ---------------- round-to-tf32 pre-pass -------------------------------------
__global__ void round_k(const float4* __restrict__ in, float4* __restrict__ out, int n4) {
    int i = blockIdx.x * blockDim.x + threadIdx.x;
    if (i < n4) {
        float4 a = in[i];
        a.x = rtf32(a.x); a.y = rtf32(a.y); a.z = rtf32(a.z); a.w = rtf32(a.w);
        out[i] = a;
    }
}

// ---------------- entity head (fp32 FFMA, tiny) -------------------------------
__global__ __launch_bounds__(256) void ent_kernel(
    const float* __restrict__ hproj, const float* __restrict__ W_ent,
    const float* __restrict__ b_ent, float* __restrict__ out)
{
    const int warp = threadIdx.x >> 5;
    const int lane = threadIdx.x & 31;
    const int row = blockIdx.x * 8 + warp;
    const float* hp = hproj + (long)row * Hn;

    float acc[En];
#pragma unroll
    for (int e = 0; e < En; ++e) acc[e] = 0.0f;
    for (int k = lane; k < Hn; k += 32) {
        const float hv = hp[k];
#pragma unroll
        for (int e = 0; e < En; ++e) acc[e] = fmaf(hv, W_ent[e * Hn + k], acc[e]);
    }
#pragma unroll
    for (int e = 0; e < En; ++e)
#pragma unroll
        for (int o = 16; o > 0; o >>= 1)
            acc[e] += __shfl_xor_sync(0xffffffffu, acc[e], o);
    if (lane == 0) {
        float* o = out + (long)row * En;
#pragma unroll
        for (int e = 0; e < En; ++e) o[e] = acc[e] + b_ent[e];
    }
}

// ---------------- host --------------------------------------------------------
extern "C" void kernel_launch(void* const* d_in, const int* in_sizes, int n_in,
                              void* d_out, int out_size)
{
    const float* h      = (const float*)d_in[0];
    const float* W_proj = (const float*)d_in[1];
    const float* b_proj = (const float*)d_in[2];
    const float* W_ent  = (const float*)d_in[3];
    const float* b_ent  = (const float*)d_in[4];
    const float* W_bil  = (const float*)d_in[5];
    const float* b_bil  = (const float*)d_in[6];
    float* out = (float*)d_out;

    float *hr, *wpr, *wbr, *hproj, *tbuf;
    cudaGetSymbolAddress((void**)&hr, g_hr);
    cudaGetSymbolAddress((void**)&wpr, g_wpr);
    cudaGetSymbolAddress((void**)&wbr, g_wbr);
    cudaGetSymbolAddress((void**)&hproj, g_hproj);
    cudaGetSymbolAddress((void**)&tbuf, g_t);

    cudaFuncSetAttribute(gemm_mma, cudaFuncAttributeMaxDynamicSharedMemorySize, SMEM_BYTES);

    // 0) round inputs to nearest-tf32 (zero-mean rounding error)
    {
        int n4;
        n4 = Bn * Ln * Hn / 4;  round_k<<<(n4 + 255) / 256, 256>>>((const float4*)h, (float4*)hr, n4);
        n4 = Hn * Hn / 4;       round_k<<<(n4 + 255) / 256, 256>>>((const float4*)W_proj, (float4*)wpr, n4);
        n4 = Rn * Hn * Hn / 4;  round_k<<<(n4 + 255) / 256, 256>>>((const float4*)W_bil, (float4*)wbr, n4);
    }

    const long entOff = (long)Bn * Ln * En;  // 20480

    // 1) hproj = rtf32(relu(h @ W_proj^T + b_proj))   M=2048 N=768 K=768
    {
        dim3 grid(Hn / BN, (Bn * Ln) / BM, 1);
        gemm_mma<<<grid, NTHR, SMEM_BYTES>>>(
            hr, 0,
            wpr, 1, 0,
            hproj, 0, 0, (long)Hn, 1,
            b_proj, /*relu|round|biasN*/ 7, Hn);
    }

    // 2) ent_logits (fp32 FFMA)
    ent_kernel<<<(Bn * Ln) / 8, 256>>>(hproj, W_ent, b_ent, out);

    // 3) t[z] = rtf32(P_{z/10} @ W_bil[z%10]^T)   M=512 N=768 K=768, 40 batches
    {
        dim3 grid(Hn / BN, Ln / BM, Bn * Rn);
        gemm_mma<<<grid, NTHR, SMEM_BYTES>>>(
            hproj, (long)Ln * Hn,
            wbr, Rn, (long)Hn * Hn,
            tbuf, (long)Rn * Ln * Hn, (long)Ln * Hn, (long)Hn, 1,
            nullptr, /*round*/ 2, Hn);
    }

    // 4) rel[b,l,m,r] = P_b @ t[b,r]^T + b_bil[r]   M=512 N=512 K=768, 40 batches
    {
        dim3 grid(Ln / BN, Ln / BM, Bn * Rn);
        gemm_mma<<<grid, NTHR, SMEM_BYTES>>>(
            hproj, (long)Ln * Hn,
            tbuf, Bn * Rn, (long)Ln * Hn,
            out + entOff, (long)Ln * Ln * Rn, 1, (long)Ln * Rn, (long)Rn,
            b_bil, /*biasZ*/ 8, Hn);
    }
}

// round 5
// speedup vs baseline: 1.1554x; 1.1554x over previous
#include <cuda_runtime.h>
#include <cstdint>

// Problem constants
#define Bn 4
#define Ln 512
#define Hn 768
#define En 10
#define Rn 10

// GEMM tiling: CTA 128x128, 8 warps of 64x32, BK=32, 3-stage cp.async
// __launch_bounds__(256, 2) -> <=128 regs, 2 CTAs/SM (smem 2x110.6KB fits 228KB)
#define BM 128
#define BN 128
#define BK 32
#define NSTAGES 3
#define NTHR 256
#define SROW 36                          // padded row stride (floats)
#define A_BYTES (BM * SROW * 4)          // 18432
#define STAGE_BYTES (2 * A_BYTES)        // 36864
#define SMEM_BYTES (NSTAGES * STAGE_BYTES)  // 110592

// ---------------- scratch (device globals: allocation-guard safe) ----------
__device__ float g_hr[Bn * Ln * Hn];        // rounded h
__device__ float g_wpr[Hn * Hn];            // rounded W_proj
__device__ float g_wbr[Rn * Hn * Hn];       // rounded W_bil
__device__ float g_hproj[Bn * Ln * Hn];     // hproj (tf32-rounded)
__device__ float g_t[Bn * Rn * Ln * Hn];    // t (tf32-rounded)

// ---------------- helpers ----------------------------------------------------
__device__ __forceinline__ uint32_t smem_u32(const void* p) {
    uint32_t a;
    asm("{ .reg .u64 t; cvta.to.shared.u64 t, %1; cvt.u32.u64 %0, t; }" : "=r"(a) : "l"(p));
    return a;
}

__device__ __forceinline__ void cp16(uint32_t saddr, const void* g) {
    asm volatile("cp.async.cg.shared.global [%0], [%1], 16;" :: "r"(saddr), "l"(g));
}
#define CP_COMMIT() asm volatile("cp.async.commit_group;" ::: "memory")
#define CP_WAIT1()  asm volatile("cp.async.wait_group 1;" ::: "memory")

__device__ __forceinline__ float rtf32(float x) {
    uint32_t u;
    asm("cvt.rna.tf32.f32 %0, %1;" : "=r"(u) : "f"(x));
    return __uint_as_float(u);
}

__device__ __forceinline__ void mma8(float* c, const uint32_t* a, const uint32_t* b) {
    asm volatile(
        "mma.sync.aligned.m16n8k8.row.col.f32.tf32.tf32.f32 "
        "{%0,%1,%2,%3}, {%4,%5,%6,%7}, {%8,%9}, {%0,%1,%2,%3};"
        : "+f"(c[0]), "+f"(c[1]), "+f"(c[2]), "+f"(c[3])
        : "r"(a[0]), "r"(a[1]), "r"(a[2]), "r"(a[3]), "r"(b[0]), "r"(b[1]));
}

// LDS via explicit shared-state-space asm (keeps addresses as 32-bit regs)
__device__ __forceinline__ uint32_t lds32(uint32_t addr) {
    uint32_t v;
    asm volatile("ld.shared.b32 %0, [%1];" : "=r"(v) : "r"(addr));
    return v;
}

// ---------------- tf32 mma.sync GEMM ------------------------------------------
// C[row, col] = sum_k A[za][row,k] * B[zb][col,k]   (A,B both K-major)
// za = z / 10, zb = z % bZmod
// C addr: C + (z/10)*cZ1 + (z%10)*cZ2 + row*sCm + col*sCn
// mode: 1=relu, 2=round-to-tf32, 4=bias[col], 8=bias[z%10]
__global__ void __launch_bounds__(NTHR, 2) gemm_mma(
    const float* __restrict__ A, long sAz,
    const float* __restrict__ B, int bZmod, long sBz,
    float* __restrict__ C, long cZ1, long cZ2, long sCm, long sCn,
    const float* __restrict__ bias, int mode, int K)
{
    extern __shared__ __align__(16) char smem[];
    const uint32_t sbase = smem_u32(smem);
    const int tid = threadIdx.x;
    const int z = blockIdx.z;
    const int m0 = blockIdx.y * BM;
    const int n0 = blockIdx.x * BN;
    const int nk = K / BK;

    const float* Ag = A + (long)(z / 10) * sAz + (long)m0 * K;
    const float* Bg = B + (long)(z % bZmod) * sBz + (long)n0 * K;

    const int wid = tid >> 5;
    const int lane = tid & 31;
    const int warp_m = wid >> 2;      // 0..1 -> 64 rows each
    const int warp_n = wid & 3;       // 0..3 -> 32 cols each
    const int g = lane >> 2;          // 0..7
    const int t = lane & 3;           // 0..3

    float acc[4][4][4];
#pragma unroll
    for (int mi = 0; mi < 4; ++mi)
#pragma unroll
        for (int ni = 0; ni < 4; ++ni)
#pragma unroll
            for (int q = 0; q < 4; ++q) acc[mi][ni][q] = 0.0f;

    // per-thread cp.async source/dest (reused every stage)
    const int ld_row = tid >> 3;               // 0..31
    const int ld_seg = (tid & 7) * 4;          // 0,4,...,28
    const float* AgT = Ag + (long)ld_row * K + ld_seg;
    const float* BgT = Bg + (long)ld_row * K + ld_seg;
    const uint32_t sOffT = (uint32_t)(ld_row * SROW + ld_seg) * 4;
    const uint32_t rowStepS = 32u * SROW * 4u;

    auto load_stage = [&](int s, int k0) {
        const uint32_t sA = sbase + s * STAGE_BYTES + sOffT;
        const uint32_t sB = sA + A_BYTES;
#pragma unroll
        for (int it = 0; it < 4; ++it) {
            cp16(sA + it * rowStepS, AgT + (long)(it * 32) * K + k0);
            cp16(sB + it * rowStepS, BgT + (long)(it * 32) * K + k0);
        }
    };

    // prefetch
    load_stage(0, 0); CP_COMMIT();
    if (nk > 1) load_stage(1, BK);
    CP_COMMIT();

    // fragment base addresses (32-bit smem offsets)
    const uint32_t aBase = (uint32_t)((warp_m * 64 + g) * SROW + t) * 4;
    const uint32_t bBase = (uint32_t)((warp_n * 32 + g) * SROW + t) * 4;

    for (int i = 0; i < nk; ++i) {
        CP_WAIT1();
        __syncthreads();
        if (i + 2 < nk) load_stage((i + 2) % NSTAGES, (i + 2) * BK);
        CP_COMMIT();

        const uint32_t sA = sbase + (i % NSTAGES) * STAGE_BYTES;
        const uint32_t sB = sA + A_BYTES;

#pragma unroll
        for (int ks = 0; ks < BK; ks += 8) {
            uint32_t af[4][4], bf[4][2];
#pragma unroll
            for (int mi = 0; mi < 4; ++mi) {
                const uint32_t p = sA + aBase + (uint32_t)(mi * 16 * SROW + ks) * 4;
                af[mi][0] = lds32(p);
                af[mi][1] = lds32(p + 8 * SROW * 4);
                af[mi][2] = lds32(p + 16);
                af[mi][3] = lds32(p + 8 * SROW * 4 + 16);
            }
#pragma unroll
            for (int ni = 0; ni < 4; ++ni) {
                const uint32_t p = sB + bBase + (uint32_t)(ni * 8 * SROW + ks) * 4;
                bf[ni][0] = lds32(p);
                bf[ni][1] = lds32(p + 16);
            }
#pragma unroll
            for (int mi = 0; mi < 4; ++mi)
#pragma unroll
                for (int ni = 0; ni < 4; ++ni)
                    mma8(acc[mi][ni], af[mi], bf[ni]);
        }
    }

    // ---------------- epilogue ----------------
    float bz = 0.0f;
    if (mode & 8) bz = bias[z % 10];
    float* Cz = C + (long)(z / 10) * cZ1 + (long)(z % 10) * cZ2;

#pragma unroll
    for (int mi = 0; mi < 4; ++mi) {
        const long r0 = m0 + warp_m * 64 + mi * 16 + g;
#pragma unroll
        for (int ni = 0; ni < 4; ++ni) {
            const long col = n0 + warp_n * 32 + ni * 8 + 2 * t;
            float v[4];
#pragma unroll
            for (int q = 0; q < 4; ++q) v[q] = acc[mi][ni][q];
            if (mode & 4) {
                const float b0v = bias[col], b1v = bias[col + 1];
                v[0] += b0v; v[1] += b1v; v[2] += b0v; v[3] += b1v;
            }
            if (mode & 8) { v[0] += bz; v[1] += bz; v[2] += bz; v[3] += bz; }
            if (mode & 1) {
#pragma unroll
                for (int q = 0; q < 4; ++q) v[q] = fmaxf(v[q], 0.0f);
            }
            if (mode & 2) {
#pragma unroll
                for (int q = 0; q < 4; ++q) v[q] = rtf32(v[q]);
            }
            if (sCn == 1) {
                *(float2*)(Cz + r0 * sCm + col) = make_float2(v[0], v[1]);
                *(float2*)(Cz + (r0 + 8) * sCm + col) = make_float2(v[2], v[3]);
            } else {
                float* p0 = Cz + r0 * sCm + col * sCn;
                float* p1 = Cz + (r0 + 8) * sCm + col * sCn;
                p0[0] = v[0]; p0[sCn] = v[1];
                p1[0] = v[2]; p1[sCn] = v[3];
            }
        }
    }
}

// ---------------- round-to-tf32 pre-pass -------------------------------------
__global__ void round_k(const float4* __restrict__ in, float4* __restrict__ out, int n4) {
    int i = blockIdx.x * blockDim.x + threadIdx.x;
    if (i < n4) {
        float4 a = in[i];
        a.x = rtf32(a.x); a.y = rtf32(a.y); a.z = rtf32(a.z); a.w = rtf32(a.w);
        out[i] = a;
    }
}

// ---------------- entity head (fp32 FFMA, tiny) -------------------------------
__global__ __launch_bounds__(256) void ent_kernel(
    const float* __restrict__ hproj, const float* __restrict__ W_ent,
    const float* __restrict__ b_ent, float* __restrict__ out)
{
    const int warp = threadIdx.x >> 5;
    const int lane = threadIdx.x & 31;
    const int row = blockIdx.x * 8 + warp;
    const float* hp = hproj + (long)row * Hn;

    float acc[En];
#pragma unroll
    for (int e = 0; e < En; ++e) acc[e] = 0.0f;
    for (int k = lane; k < Hn; k += 32) {
        const float hv = hp[k];
#pragma unroll
        for (int e = 0; e < En; ++e) acc[e] = fmaf(hv, W_ent[e * Hn + k], acc[e]);
    }
#pragma unroll
    for (int e = 0; e < En; ++e)
#pragma unroll
        for (int o = 16; o > 0; o >>= 1)
            acc[e] += __shfl_xor_sync(0xffffffffu, acc[e], o);
    if (lane == 0) {
        float* o = out + (long)row * En;
#pragma unroll
        for (int e = 0; e < En; ++e) o[e] = acc[e] + b_ent[e];
    }
}

// ---------------- host --------------------------------------------------------
extern "C" void kernel_launch(void* const* d_in, const int* in_sizes, int n_in,
                              void* d_out, int out_size)
{
    const float* h      = (const float*)d_in[0];
    const float* W_proj = (const float*)d_in[1];
    const float* b_proj = (const float*)d_in[2];
    const float* W_ent  = (const float*)d_in[3];
    const float* b_ent  = (const float*)d_in[4];
    const float* W_bil  = (const float*)d_in[5];
    const float* b_bil  = (const float*)d_in[6];
    float* out = (float*)d_out;

    float *hr, *wpr, *wbr, *hproj, *tbuf;
    cudaGetSymbolAddress((void**)&hr, g_hr);
    cudaGetSymbolAddress((void**)&wpr, g_wpr);
    cudaGetSymbolAddress((void**)&wbr, g_wbr);
    cudaGetSymbolAddress((void**)&hproj, g_hproj);
    cudaGetSymbolAddress((void**)&tbuf, g_t);

    cudaFuncSetAttribute(gemm_mma, cudaFuncAttributeMaxDynamicSharedMemorySize, SMEM_BYTES);

    // 0) round inputs to nearest-tf32 (zero-mean rounding error)
    {
        int n4;
        n4 = Bn * Ln * Hn / 4;  round_k<<<(n4 + 255) / 256, 256>>>((const float4*)h, (float4*)hr, n4);
        n4 = Hn * Hn / 4;       round_k<<<(n4 + 255) / 256, 256>>>((const float4*)W_proj, (float4*)wpr, n4);
        n4 = Rn * Hn * Hn / 4;  round_k<<<(n4 + 255) / 256, 256>>>((const float4*)W_bil, (float4*)wbr, n4);
    }

    const long entOff = (long)Bn * Ln * En;  // 20480

    // 1) hproj = rtf32(relu(h @ W_proj^T + b_proj))   M=2048 N=768 K=768
    {
        dim3 grid(Hn / BN, (Bn * Ln) / BM, 1);
        gemm_mma<<<grid, NTHR, SMEM_BYTES>>>(
            hr, 0,
            wpr, 1, 0,
            hproj, 0, 0, (long)Hn, 1,
            b_proj, /*relu|round|biasN*/ 7, Hn);
    }

    // 2) ent_logits (fp32 FFMA)
    ent_kernel<<<(Bn * Ln) / 8, 256>>>(hproj, W_ent, b_ent, out);

    // 3) t[z] = rtf32(P_{z/10} @ W_bil[z%10]^T)   M=512 N=768 K=768, 40 batches
    {
        dim3 grid(Hn / BN, Ln / BM, Bn * Rn);
        gemm_mma<<<grid, NTHR, SMEM_BYTES>>>(
            hproj, (long)Ln * Hn,
            wbr, Rn, (long)Hn * Hn,
            tbuf, (long)Rn * Ln * Hn, (long)Ln * Hn, (long)Hn, 1,
            nullptr, /*round*/ 2, Hn);
    }

    // 4) rel[b,l,m,r] = P_b @ t[b,r]^T + b_bil[r]   M=512 N=512 K=768, 40 batches
    {
        dim3 grid(Ln / BN, Ln / BM, Bn * Rn);
        gemm_mma<<<grid, NTHR, SMEM_BYTES>>>(
            hproj, (long)Ln * Hn,
            tbuf, Bn * Rn, (long)Ln * Hn,
            out + entOff, (long)Ln * Ln * Rn, 1, (long)Ln * Rn, (long)Rn,
            b_bil, /*biasZ*/ 8, Hn);
    }
}